// round 16
// baseline (speedup 1.0000x reference)
#include <cuda_runtime.h>

#define NN 50000
#define MM 800000
#define DIMC 64
#define D2 128
#define EPSM 1e-7f
#define BN_EPS 1e-5f
#define NBS ((NN + 255) / 256)   // 196 blocks (all co-resident: grid-sync safe)

// ---------------- scratch (static device allocations; zero-initialized at load) ----------------
__device__ int g_sync1;
__device__ int g_sync2;
__device__ int g_deg[NN];                     // re-zeroed inside scanscatter each replay
__device__ int g_rowptr[NN + 1];
__device__ int g_cursor[NN];
__device__ int g_bsum[NBS];
__device__ int2 g_epair[MM];                  // (edge id, src) in CSR order
__device__ double g_stats[3][2 * D2];         // per-layer: sum | sumsq
__device__ float g_h[(size_t)NN * DIMC];      // agg + x  (GEMM1 input)
__device__ float g_h1[(size_t)NN * D2];       // GEMM1 output
__device__ float g_xb[2][(size_t)NN * DIMC];  // ping-pong x

// ---------------- f32x2 packed helpers ----------------
__device__ __forceinline__ unsigned long long pack2(float a, float b) {
    unsigned long long r;
    asm("mov.b64 %0, {%1, %2};" : "=l"(r) : "f"(a), "f"(b));
    return r;
}
__device__ __forceinline__ void unpack2(unsigned long long v, float& a, float& b) {
    asm("mov.b64 {%0, %1}, %2;" : "=f"(a), "=f"(b) : "l"(v));
}
__device__ __forceinline__ void fma2(unsigned long long& d, unsigned long long a,
                                     unsigned long long b) {
    asm("fma.rn.f32x2 %0, %1, %2, %0;" : "+l"(d) : "l"(a), "l"(b));
}

// edge index load robust to int32 vs int64 storage
__device__ __forceinline__ int load_idx(const void* ei, size_t pos, int is64) {
    if (is64) return (int)((const long long*)ei)[pos];
    return ((const int*)ei)[pos];
}

// per-block dtype detection: int64 values in [0,50000) -> odd 32-bit words are 0
__device__ __forceinline__ int detect_is64(const unsigned* __restrict__ w) {
    __shared__ int sflag;
    if (threadIdx.x < 32) {
        int zeros = 0;
        for (int j = threadIdx.x; j < 256; j += 32)
            if (w[2 * j + 1] == 0u) zeros++;
        for (int o = 16; o; o >>= 1) zeros += __shfl_down_sync(0xffffffffu, zeros, o);
        if (threadIdx.x == 0) sflag = (zeros > 200) ? 1 : 0;
    }
    __syncthreads();
    return sflag;
}

// ---------------- launch 0: fused init + hist ----------------
__global__ void inithist_kernel(const void* __restrict__ ei, int* __restrict__ deg,
                                double* __restrict__ stats, int* __restrict__ sync1,
                                int* __restrict__ sync2) {
    int is64 = detect_is64((const unsigned*)ei);
    if (blockIdx.x == 0) {
        for (int i = threadIdx.x; i < 3 * 2 * D2; i += 256) stats[i] = 0.0;
        if (threadIdx.x == 0) { *sync1 = 0; *sync2 = 0; }
    }
    for (int i = blockIdx.x * blockDim.x + threadIdx.x; i < MM; i += gridDim.x * blockDim.x)
        atomicAdd(&deg[load_idx(ei, (size_t)MM + i, is64)], 1);
}

// ---------------- launch 1: fused scan + scatter, grid-synchronized ----------------
__global__ __launch_bounds__(256) void scanscatter_kernel(
        int* __restrict__ deg, int* __restrict__ rowptr, int* __restrict__ cursor,
        int* __restrict__ bsum, const void* __restrict__ ei, int2* __restrict__ epair,
        int* __restrict__ sync1, int* __restrict__ sync2) {
    __shared__ int sh[256];
    int is64 = detect_is64((const unsigned*)ei);
    int t = threadIdx.x;
    int b = blockIdx.x;
    int i = b * 256 + t;
    // Phase A: per-block inclusive scan of deg
    int v = (i < NN) ? deg[i] : 0;
    sh[t] = v;
    __syncthreads();
    for (int off = 1; off < 256; off <<= 1) {
        int cur = sh[t];
        int u = (t >= off) ? sh[t - off] : 0;
        __syncthreads();
        sh[t] = cur + u;
        __syncthreads();
    }
    int excl = sh[t] - v;
    if (t == 255) bsum[b] = sh[t];
    __threadfence();
    __syncthreads();
    if (t == 0) {
        atomicAdd(sync1, 1);
        while (*(volatile int*)sync1 < NBS) { }
    }
    __syncthreads();
    // re-zero deg for the next replay (own indices; all reads happened pre-barrier)
    if (i < NN) deg[i] = 0;
    // Phase B: block offset = sum of bsum[0..b)
    int s = (t < NBS && t < b) ? bsum[t] : 0;
    sh[t] = s;
    __syncthreads();
    for (int off = 128; off; off >>= 1) {
        if (t < off) sh[t] += sh[t + off];
        __syncthreads();
    }
    int offset = sh[0];
    if (i < NN) {
        int r = offset + excl;
        rowptr[i] = r;
        cursor[i] = r;
    }
    if (i == 0) rowptr[NN] = MM;
    __threadfence();
    __syncthreads();
    if (t == 0) {
        atomicAdd(sync2, 1);
        while (*(volatile int*)sync2 < NBS) { }
    }
    __syncthreads();
    // Phase C: scatter edges (grid-stride)
    for (int e = b * 256 + t; e < MM; e += NBS * 256) {
        int d = load_idx(ei, (size_t)MM + e, is64);
        int sv = load_idx(ei, (size_t)e, is64);
        int p = atomicAdd(&cursor[d], 1);
        epair[p] = make_int2(e, sv);
    }
}

// ---------------- launch 2: softmax aggregation + residual (one warp / node) ----------------
// Shift-free softmax: msg in [eps, ~15] keeps exp/sums safely in fp32 range,
// so alphas are identical to the max-subtracted formulation. (R11-proven form.)
__global__ void agg_kernel(const float* __restrict__ x, const float* __restrict__ ea,
                           const int* __restrict__ rowptr, const int2* __restrict__ epair,
                           float* __restrict__ h) {
    int warp = (blockIdx.x * blockDim.x + threadIdx.x) >> 5;
    int lane = threadIdx.x & 31;
    if (warp >= NN) return;
    int n = warp;
    int c0 = lane, c1 = lane + 32;
    float s0 = 0.f, s1 = 0.f, w0 = 0.f, w1 = 0.f;
    int beg = rowptr[n], end = rowptr[n + 1];
    #pragma unroll 4
    for (int j = beg; j < end; j++) {
        int2 p = __ldcs(&epair[j]);               // sequential LDG.64, streaming
        const float* xs = x + (size_t)p.y * DIMC; // L2-resident gather
        const float* ep = ea + (size_t)p.x * DIMC;// full-line gather, streaming
        float m0 = fmaxf(xs[c0] + __ldcs(&ep[c0]), 0.f) + EPSM;
        float m1 = fmaxf(xs[c1] + __ldcs(&ep[c1]), 0.f) + EPSM;
        float t0 = __expf(m0);
        float t1 = __expf(m1);
        s0 += t0; w0 += m0 * t0;
        s1 += t1; w1 += m1 * t1;
    }
    float a0 = w0 / fmaxf(s0, 1e-16f);
    float a1 = w1 / fmaxf(s1, 1e-16f);
    h[(size_t)n * DIMC + c0] = a0 + x[(size_t)n * DIMC + c0];
    h[(size_t)n * DIMC + c1] = a1 + x[(size_t)n * DIMC + c1];
}

// ---------------- launch 3 (profiled): GEMM1 h[N,64] @ W1[64,128] + b1, with BN stats ----------------
// 64-node tile, 256 threads; per-thread tile 4 nodes x 8 cols (two 4-col groups at
// smem offsets tx*4 and 64+tx*4 -> both LDS.128 at 16B lane stride, conflict-free).
// Per k: 2 LDS.128 (W) + 4 LDS.64 (H) + 16 FFMA2 -> FMA-dense.
__global__ __launch_bounds__(256) void gemm1_kernel(
        const float* __restrict__ h, const float* __restrict__ W1,
        const float* __restrict__ b1, float* __restrict__ h1,
        double* __restrict__ gstats) {
    __shared__ unsigned long long Hsd[64][DIMC];     // 32KB: (h,h) duplicated
    __shared__ float Ws[32][D2];                     // 16KB; stats alias post-loop
    int tid = threadIdx.x;
    int n0 = blockIdx.x * 64;
    for (int i = tid; i < 64 * DIMC / 2; i += 256) { // float2 loads, coalesced
        int n = i >> 5, k2 = (i & 31) * 2;
        float2 v = make_float2(0.f, 0.f);
        if (n0 + n < NN) v = *(const float2*)(h + (size_t)(n0 + n) * DIMC + k2);
        Hsd[n][k2] = pack2(v.x, v.x);
        Hsd[n][k2 + 1] = pack2(v.y, v.y);
    }
    int tx = tid & 15;    // 8 cols each: {tx*4..tx*4+3} and {64+tx*4..64+tx*4+3}
    int ty = tid >> 4;    // 0..15, 4 nodes each -> 64
    float4 bva = ((const float4*)b1)[tx];
    float4 bvb = ((const float4*)b1)[16 + tx];
    unsigned long long acc[4][4];
    #pragma unroll
    for (int i = 0; i < 4; i++) {
        acc[i][0] = pack2(bva.x, bva.y); acc[i][1] = pack2(bva.z, bva.w);
        acc[i][2] = pack2(bvb.x, bvb.y); acc[i][3] = pack2(bvb.z, bvb.w);
    }
    #pragma unroll 1
    for (int ph = 0; ph < 2; ph++) {
        if (ph) __syncthreads();                      // protect Ws before reload
        for (int i = tid; i < 32 * D2; i += 256)
            Ws[i >> 7][i & 127] = W1[ph * 32 * D2 + i];
        __syncthreads();
        int kb = ph * 32;
        #pragma unroll 8
        for (int k = 0; k < 32; k++) {
            ulonglong2 wa = *(const ulonglong2*)&Ws[k][tx * 4];       // 16B stride
            ulonglong2 wb = *(const ulonglong2*)&Ws[k][64 + tx * 4];  // 16B stride
            int kg = kb + k;
            #pragma unroll
            for (int i = 0; i < 4; i++) {
                unsigned long long h2 = Hsd[ty * 4 + i][kg];          // 2-way broadcast
                fma2(acc[i][0], h2, wa.x);
                fma2(acc[i][1], h2, wa.y);
                fma2(acc[i][2], h2, wb.x);
                fma2(acc[i][3], h2, wb.y);
            }
        }
    }
    __syncthreads();
    // stats region aliased into Ws (dead after k-loop); same type, no punning
    float* ssum = &Ws[0][0];
    float* ssq = ssum + D2;
    if (tid < 2 * D2) ssum[tid] = 0.f;
    __syncthreads();
    float ls[8] = {0, 0, 0, 0, 0, 0, 0, 0};
    float lq[8] = {0, 0, 0, 0, 0, 0, 0, 0};
    #pragma unroll
    for (int i = 0; i < 4; i++) {
        int n = n0 + ty * 4 + i;
        if (n < NN) {
            float4 va, vb;
            unpack2(acc[i][0], va.x, va.y);
            unpack2(acc[i][1], va.z, va.w);
            unpack2(acc[i][2], vb.x, vb.y);
            unpack2(acc[i][3], vb.z, vb.w);
            *(float4*)(h1 + (size_t)n * D2 + tx * 4) = va;
            *(float4*)(h1 + (size_t)n * D2 + 64 + tx * 4) = vb;
            ls[0] += va.x; ls[1] += va.y; ls[2] += va.z; ls[3] += va.w;
            ls[4] += vb.x; ls[5] += vb.y; ls[6] += vb.z; ls[7] += vb.w;
            lq[0] += va.x * va.x; lq[1] += va.y * va.y; lq[2] += va.z * va.z; lq[3] += va.w * va.w;
            lq[4] += vb.x * vb.x; lq[5] += vb.y * vb.y; lq[6] += vb.z * vb.z; lq[7] += vb.w * vb.w;
        }
    }
    #pragma unroll
    for (int q = 0; q < 4; q++) {
        atomicAdd(&ssum[tx * 4 + q], ls[q]);      atomicAdd(&ssq[tx * 4 + q], lq[q]);
        atomicAdd(&ssum[64 + tx * 4 + q], ls[4 + q]); atomicAdd(&ssq[64 + tx * 4 + q], lq[4 + q]);
    }
    __syncthreads();
    if (tid < D2) {
        atomicAdd(&gstats[tid], (double)ssum[tid]);
        atomicAdd(&gstats[D2 + tid], (double)ssq[tid]);
    }
}

// ---------------- GEMM2: relu(BN(h1)) @ W2[128,64] + b2; BN folded, per-thread reg scales ----------------
__global__ __launch_bounds__(256) void gemm2_kernel(
        const float* __restrict__ h1, const double* __restrict__ gstats,
        const float* __restrict__ gamma, const float* __restrict__ beta,
        const float* __restrict__ W2, const float* __restrict__ b2,
        float* __restrict__ out) {
    __shared__ float Hs[64][D2];          // 32KB, node-major, BN+relu applied at load
    __shared__ float Ws[64][DIMC];        // 16KB (one 64-k phase)
    int tid = threadIdx.x;
    int n0 = blockIdx.x * 64;
    // per-thread BN constants for its fixed k-quad
    int kq = (tid & 31) * 4;
    float scr[4], shr[4];
    const double innr = 1.0 / (double)NN;
    #pragma unroll
    for (int q = 0; q < 4; q++) {
        int k = kq + q;
        double mu = gstats[k] * innr;
        double var = gstats[D2 + k] * innr - mu * mu;
        float inv = rsqrtf((float)var + BN_EPS);
        float sc = inv * gamma[k];
        scr[q] = sc;
        shr[q] = beta[k] - (float)mu * sc;
    }
    #pragma unroll
    for (int s = 0; s < 8; s++) {
        int n = (tid >> 5) + s * 8;
        float4 v = make_float4(0.f, 0.f, 0.f, 0.f);
        if (n0 + n < NN) {
            v = *(const float4*)(h1 + (size_t)(n0 + n) * D2 + kq);
            v.x = fmaxf(v.x * scr[0] + shr[0], 0.f);
            v.y = fmaxf(v.y * scr[1] + shr[1], 0.f);
            v.z = fmaxf(v.z * scr[2] + shr[2], 0.f);
            v.w = fmaxf(v.w * scr[3] + shr[3], 0.f);
        }
        *(float4*)&Hs[n][kq] = v;
    }
    int tx = tid & 15;    // 4 output cols each
    int ty = tid >> 4;    // 4 nodes each
    float4 bv = ((const float4*)b2)[tx];
    unsigned long long acc[4][2];
    #pragma unroll
    for (int i = 0; i < 4; i++) { acc[i][0] = pack2(bv.x, bv.y); acc[i][1] = pack2(bv.z, bv.w); }
    #pragma unroll 1
    for (int ph = 0; ph < 2; ph++) {
        if (ph) __syncthreads();                      // protect Ws before reload
        for (int i = tid; i < 64 * DIMC; i += 256)
            Ws[i >> 6][i & 63] = W2[ph * 64 * DIMC + i];
        __syncthreads();
        int kb = ph * 64;
        #pragma unroll 16
        for (int k = 0; k < 64; k++) {
            ulonglong2 wv = *(const ulonglong2*)&Ws[k][tx * 4];  // 16B stride: conflict-free
            int kg = kb + k;
            #pragma unroll
            for (int i = 0; i < 4; i++) {
                float hv = Hs[ty * 4 + i][kg];   // warp-broadcast
                unsigned long long hh = pack2(hv, hv);
                fma2(acc[i][0], hh, wv.x);
                fma2(acc[i][1], hh, wv.y);
            }
        }
    }
    #pragma unroll
    for (int i = 0; i < 4; i++) {
        int n = n0 + ty * 4 + i;
        if (n < NN) {
            float a, b;
            float4 v;
            unpack2(acc[i][0], a, b); v.x = a; v.y = b;
            unpack2(acc[i][1], a, b); v.z = a; v.w = b;
            *(float4*)(out + (size_t)n * DIMC + tx * 4) = v;
        }
    }
}

// ---------------- host launcher ----------------
extern "C" void kernel_launch(void* const* d_in, const int* in_sizes, int n_in,
                              void* d_out, int out_size) {
    const float* x_in = (const float*)d_in[0];
    const void* ei = d_in[1];
    const float* ea = (const float*)d_in[2];
    const float* W1 = (const float*)d_in[3];
    const float* b1 = (const float*)d_in[4];
    const float* gamma = (const float*)d_in[5];
    const float* beta = (const float*)d_in[6];
    const float* W2 = (const float*)d_in[7];
    const float* b2 = (const float*)d_in[8];
    float* out = (float*)d_out;

    void *p_s1, *p_s2, *p_deg, *p_rowptr, *p_cursor, *p_bsum, *p_epair;
    void *p_stats, *p_h, *p_h1, *p_xb;
    cudaGetSymbolAddress(&p_s1, g_sync1);
    cudaGetSymbolAddress(&p_s2, g_sync2);
    cudaGetSymbolAddress(&p_deg, g_deg);
    cudaGetSymbolAddress(&p_rowptr, g_rowptr);
    cudaGetSymbolAddress(&p_cursor, g_cursor);
    cudaGetSymbolAddress(&p_bsum, g_bsum);
    cudaGetSymbolAddress(&p_epair, g_epair);
    cudaGetSymbolAddress(&p_stats, g_stats);
    cudaGetSymbolAddress(&p_h, g_h);
    cudaGetSymbolAddress(&p_h1, g_h1);
    cudaGetSymbolAddress(&p_xb, g_xb);

    int* sync1 = (int*)p_s1;
    int* sync2 = (int*)p_s2;
    int* deg = (int*)p_deg;
    int* rowptr = (int*)p_rowptr;
    int* cursor = (int*)p_cursor;
    int* bsum = (int*)p_bsum;
    int2* epair = (int2*)p_epair;
    double* stats = (double*)p_stats;
    float* hbuf = (float*)p_h;
    float* h1buf = (float*)p_h1;
    float* xb = (float*)p_xb;

    // launch 0: fused init+hist; launch 1: scan+scatter (re-zeroes deg for next replay)
    inithist_kernel<<<256, 256>>>(ei, deg, stats, sync1, sync2);
    scanscatter_kernel<<<NBS, 256>>>(deg, rowptr, cursor, bsum, ei, epair, sync1, sync2);

    const int NB = (NN + 63) / 64;          // 782 tiles of 64 nodes
    const int AGG_BLOCKS = (NN * 32 + 255) / 256;

    const float* xcur = x_in;
    for (int l = 0; l < 3; l++) {
        double* lstats = stats + (size_t)l * 2 * D2;
        // layer 0: agg = launch 2, gemm1 = launch 3 (profiled)
        agg_kernel<<<AGG_BLOCKS, 256>>>(xcur, ea, rowptr, epair, hbuf);
        gemm1_kernel<<<NB, 256>>>(hbuf, W1 + (size_t)l * DIMC * D2, b1 + (size_t)l * D2,
                                  h1buf, lstats);
        float* xnext = (l == 2) ? out : (xb + (size_t)(l & 1) * NN * DIMC);
        gemm2_kernel<<<NB, 256>>>(h1buf, lstats, gamma + (size_t)l * D2,
                                  beta + (size_t)l * D2, W2 + (size_t)l * D2 * DIMC,
                                  b2 + (size_t)l * DIMC, xnext);
        xcur = xnext;
    }
}

// round 17
// speedup vs baseline: 1.0935x; 1.0935x over previous
#include <cuda_runtime.h>

#define NN 50000
#define MM 800000
#define DIMC 64
#define D2 128
#define EPSM 1e-7f
#define BN_EPS 1e-5f
#define NBS ((NN + 255) / 256)   // 196 blocks (all co-resident: grid-sync safe)

// ---------------- scratch (static device allocations; zero-initialized at load) ----------------
__device__ int g_sync1;
__device__ int g_sync2;
__device__ int g_deg[NN];                     // re-zeroed inside scanscatter each replay
__device__ int g_rowptr[NN + 1];
__device__ int g_cursor[NN];
__device__ int g_bsum[NBS];
__device__ int2 g_epair[MM];                  // (edge id, src) in CSR order
__device__ double g_stats[3][2 * D2];         // per-layer: sum | sumsq
__device__ float g_h[(size_t)NN * DIMC];      // agg + x  (GEMM1 input)
__device__ float g_h1[(size_t)NN * D2];       // GEMM1 output
__device__ float g_xb[2][(size_t)NN * DIMC];  // ping-pong x

// ---------------- f32x2 packed helpers ----------------
__device__ __forceinline__ unsigned long long pack2(float a, float b) {
    unsigned long long r;
    asm("mov.b64 %0, {%1, %2};" : "=l"(r) : "f"(a), "f"(b));
    return r;
}
__device__ __forceinline__ void unpack2(unsigned long long v, float& a, float& b) {
    asm("mov.b64 {%0, %1}, %2;" : "=f"(a), "=f"(b) : "l"(v));
}
__device__ __forceinline__ void fma2(unsigned long long& d, unsigned long long a,
                                     unsigned long long b) {
    asm("fma.rn.f32x2 %0, %1, %2, %0;" : "+l"(d) : "l"(a), "l"(b));
}

// edge index load robust to int32 vs int64 storage
__device__ __forceinline__ int load_idx(const void* ei, size_t pos, int is64) {
    if (is64) return (int)((const long long*)ei)[pos];
    return ((const int*)ei)[pos];
}

// per-block dtype detection: int64 values in [0,50000) -> odd 32-bit words are 0
__device__ __forceinline__ int detect_is64(const unsigned* __restrict__ w) {
    __shared__ int sflag;
    if (threadIdx.x < 32) {
        int zeros = 0;
        for (int j = threadIdx.x; j < 256; j += 32)
            if (w[2 * j + 1] == 0u) zeros++;
        for (int o = 16; o; o >>= 1) zeros += __shfl_down_sync(0xffffffffu, zeros, o);
        if (threadIdx.x == 0) sflag = (zeros > 200) ? 1 : 0;
    }
    __syncthreads();
    return sflag;
}

// ---------------- launch 0: fused init + hist ----------------
__global__ void inithist_kernel(const void* __restrict__ ei, int* __restrict__ deg,
                                double* __restrict__ stats, int* __restrict__ sync1,
                                int* __restrict__ sync2) {
    int is64 = detect_is64((const unsigned*)ei);
    if (blockIdx.x == 0) {
        for (int i = threadIdx.x; i < 3 * 2 * D2; i += 256) stats[i] = 0.0;
        if (threadIdx.x == 0) { *sync1 = 0; *sync2 = 0; }
    }
    for (int i = blockIdx.x * blockDim.x + threadIdx.x; i < MM; i += gridDim.x * blockDim.x)
        atomicAdd(&deg[load_idx(ei, (size_t)MM + i, is64)], 1);
}

// ---------------- launch 1: fused scan + scatter, grid-synchronized ----------------
__global__ __launch_bounds__(256) void scanscatter_kernel(
        int* __restrict__ deg, int* __restrict__ rowptr, int* __restrict__ cursor,
        int* __restrict__ bsum, const void* __restrict__ ei, int2* __restrict__ epair,
        int* __restrict__ sync1, int* __restrict__ sync2) {
    __shared__ int sh[256];
    int is64 = detect_is64((const unsigned*)ei);
    int t = threadIdx.x;
    int b = blockIdx.x;
    int i = b * 256 + t;
    // Phase A: per-block inclusive scan of deg
    int v = (i < NN) ? deg[i] : 0;
    sh[t] = v;
    __syncthreads();
    for (int off = 1; off < 256; off <<= 1) {
        int cur = sh[t];
        int u = (t >= off) ? sh[t - off] : 0;
        __syncthreads();
        sh[t] = cur + u;
        __syncthreads();
    }
    int excl = sh[t] - v;
    if (t == 255) bsum[b] = sh[t];
    __threadfence();
    __syncthreads();
    if (t == 0) {
        atomicAdd(sync1, 1);
        while (*(volatile int*)sync1 < NBS) { }
    }
    __syncthreads();
    // re-zero deg for the next replay (own indices; all reads happened pre-barrier)
    if (i < NN) deg[i] = 0;
    // Phase B: block offset = sum of bsum[0..b)
    int s = (t < NBS && t < b) ? bsum[t] : 0;
    sh[t] = s;
    __syncthreads();
    for (int off = 128; off; off >>= 1) {
        if (t < off) sh[t] += sh[t + off];
        __syncthreads();
    }
    int offset = sh[0];
    if (i < NN) {
        int r = offset + excl;
        rowptr[i] = r;
        cursor[i] = r;
    }
    if (i == 0) rowptr[NN] = MM;
    __threadfence();
    __syncthreads();
    if (t == 0) {
        atomicAdd(sync2, 1);
        while (*(volatile int*)sync2 < NBS) { }
    }
    __syncthreads();
    // Phase C: scatter edges (grid-stride)
    for (int e = b * 256 + t; e < MM; e += NBS * 256) {
        int d = load_idx(ei, (size_t)MM + e, is64);
        int sv = load_idx(ei, (size_t)e, is64);
        int p = atomicAdd(&cursor[d], 1);
        epair[p] = make_int2(e, sv);
    }
}

// ---------------- launch 2 (profiled): softmax aggregation + residual (one warp / node) ----------------
// Shift-free softmax (msg in [eps,~15]: exp/sums fp32-safe, alphas identical).
// Explicit 4-edge batching: forces ptxas to buffer 16 gather results in registers,
// raising memory-level parallelism (the pragma-unroll variants kept regs=32 and stalled).
__global__ void agg_kernel(const float* __restrict__ x, const float* __restrict__ ea,
                           const int* __restrict__ rowptr, const int2* __restrict__ epair,
                           float* __restrict__ h) {
    int warp = (blockIdx.x * blockDim.x + threadIdx.x) >> 5;
    int lane = threadIdx.x & 31;
    if (warp >= NN) return;
    int n = warp;
    int c0 = lane, c1 = lane + 32;
    float s0 = 0.f, s1 = 0.f, w0 = 0.f, w1 = 0.f;
    int beg = rowptr[n], end = rowptr[n + 1];
    int j = beg;
    for (; j + 4 <= end; j += 4) {
        float xv0[4], xv1[4], ev0[4], ev1[4];
        #pragma unroll
        for (int u = 0; u < 4; u++) {
            int2 p = epair[j + u];                    // L2-resident across layers
            const float* xs = x + (size_t)p.y * DIMC; // L2-resident gather
            const float* ep = ea + (size_t)p.x * DIMC;// DRAM gather, streaming
            xv0[u] = xs[c0];
            xv1[u] = xs[c1];
            ev0[u] = __ldcs(&ep[c0]);
            ev1[u] = __ldcs(&ep[c1]);
        }
        #pragma unroll
        for (int u = 0; u < 4; u++) {
            float m0 = fmaxf(xv0[u] + ev0[u], 0.f) + EPSM;
            float m1 = fmaxf(xv1[u] + ev1[u], 0.f) + EPSM;
            float t0 = __expf(m0);
            float t1 = __expf(m1);
            s0 += t0; w0 += m0 * t0;
            s1 += t1; w1 += m1 * t1;
        }
    }
    for (; j < end; j++) {                            // tail
        int2 p = epair[j];
        const float* xs = x + (size_t)p.y * DIMC;
        const float* ep = ea + (size_t)p.x * DIMC;
        float m0 = fmaxf(xs[c0] + __ldcs(&ep[c0]), 0.f) + EPSM;
        float m1 = fmaxf(xs[c1] + __ldcs(&ep[c1]), 0.f) + EPSM;
        float t0 = __expf(m0);
        float t1 = __expf(m1);
        s0 += t0; w0 += m0 * t0;
        s1 += t1; w1 += m1 * t1;
    }
    float a0 = w0 / fmaxf(s0, 1e-16f);
    float a1 = w1 / fmaxf(s1, 1e-16f);
    h[(size_t)n * DIMC + c0] = a0 + x[(size_t)n * DIMC + c0];
    h[(size_t)n * DIMC + c1] = a1 + x[(size_t)n * DIMC + c1];
}

// ---------------- GEMM1: h[N,64] @ W1[64,128] + b1, with BN stats (R14-proven form) ----------------
__global__ __launch_bounds__(256, 4) void gemm1_kernel(
        const float* __restrict__ h, const float* __restrict__ W1,
        const float* __restrict__ b1, float* __restrict__ h1,
        double* __restrict__ gstats) {
    __shared__ unsigned long long Hsd[64][DIMC];     // 32KB: (h,h) duplicated
    __shared__ float Ws[32][D2];                     // 16KB; stats alias post-loop
    int tid = threadIdx.x;
    int n0 = blockIdx.x * 64;
    for (int i = tid; i < 64 * DIMC / 2; i += 256) { // float2 loads, coalesced
        int n = i >> 5, k2 = (i & 31) * 2;
        float2 v = make_float2(0.f, 0.f);
        if (n0 + n < NN) v = *(const float2*)(h + (size_t)(n0 + n) * DIMC + k2);
        Hsd[n][k2] = pack2(v.x, v.x);
        Hsd[n][k2 + 1] = pack2(v.y, v.y);
    }
    int tx = tid & 31;    // 4 cols each -> 128
    int ty = tid >> 5;    // 8 nodes each -> 64
    float4 bv = ((const float4*)b1)[tx];
    unsigned long long acc[8][2];
    #pragma unroll
    for (int i = 0; i < 8; i++) { acc[i][0] = pack2(bv.x, bv.y); acc[i][1] = pack2(bv.z, bv.w); }
    #pragma unroll 1
    for (int ph = 0; ph < 2; ph++) {
        if (ph) __syncthreads();                      // protect Ws before reload
        for (int i = tid; i < 32 * D2; i += 256)
            Ws[i >> 7][i & 127] = W1[ph * 32 * D2 + i];
        __syncthreads();
        int kb = ph * 32;
        #pragma unroll 16
        for (int k = 0; k < 32; k++) {
            ulonglong2 wv = *(const ulonglong2*)&Ws[k][tx * 4];  // 16B stride: conflict-free
            int kg = kb + k;
            #pragma unroll
            for (int i = 0; i < 8; i++) {
                unsigned long long h2 = Hsd[ty * 8 + i][kg];     // broadcast
                fma2(acc[i][0], h2, wv.x);
                fma2(acc[i][1], h2, wv.y);
            }
        }
    }
    __syncthreads();
    // stats region aliased into Ws (dead after k-loop); same type, no punning
    float* ssum = &Ws[0][0];
    float* ssq = ssum + D2;
    if (tid < 2 * D2) ssum[tid] = 0.f;
    __syncthreads();
    float ls0 = 0.f, ls1 = 0.f, ls2 = 0.f, ls3 = 0.f;
    float lq0 = 0.f, lq1 = 0.f, lq2 = 0.f, lq3 = 0.f;
    #pragma unroll
    for (int i = 0; i < 8; i++) {
        int n = n0 + ty * 8 + i;
        if (n < NN) {
            float4 v;
            unpack2(acc[i][0], v.x, v.y);
            unpack2(acc[i][1], v.z, v.w);
            *(float4*)(h1 + (size_t)n * D2 + tx * 4) = v;
            ls0 += v.x; ls1 += v.y; ls2 += v.z; ls3 += v.w;
            lq0 += v.x * v.x; lq1 += v.y * v.y; lq2 += v.z * v.z; lq3 += v.w * v.w;
        }
    }
    atomicAdd(&ssum[tx * 4 + 0], ls0); atomicAdd(&ssq[tx * 4 + 0], lq0);
    atomicAdd(&ssum[tx * 4 + 1], ls1); atomicAdd(&ssq[tx * 4 + 1], lq1);
    atomicAdd(&ssum[tx * 4 + 2], ls2); atomicAdd(&ssq[tx * 4 + 2], lq2);
    atomicAdd(&ssum[tx * 4 + 3], ls3); atomicAdd(&ssq[tx * 4 + 3], lq3);
    __syncthreads();
    if (tid < D2) {
        atomicAdd(&gstats[tid], (double)ssum[tid]);
        atomicAdd(&gstats[D2 + tid], (double)ssq[tid]);
    }
}

// ---------------- GEMM2: relu(BN(h1)) @ W2[128,64] + b2; BN folded, per-thread reg scales ----------------
__global__ __launch_bounds__(256) void gemm2_kernel(
        const float* __restrict__ h1, const double* __restrict__ gstats,
        const float* __restrict__ gamma, const float* __restrict__ beta,
        const float* __restrict__ W2, const float* __restrict__ b2,
        float* __restrict__ out) {
    __shared__ float Hs[64][D2];          // 32KB, node-major, BN+relu applied at load
    __shared__ float Ws[64][DIMC];        // 16KB (one 64-k phase)
    int tid = threadIdx.x;
    int n0 = blockIdx.x * 64;
    // per-thread BN constants for its fixed k-quad
    int kq = (tid & 31) * 4;
    float scr[4], shr[4];
    const double innr = 1.0 / (double)NN;
    #pragma unroll
    for (int q = 0; q < 4; q++) {
        int k = kq + q;
        double mu = gstats[k] * innr;
        double var = gstats[D2 + k] * innr - mu * mu;
        float inv = rsqrtf((float)var + BN_EPS);
        float sc = inv * gamma[k];
        scr[q] = sc;
        shr[q] = beta[k] - (float)mu * sc;
    }
    #pragma unroll
    for (int s = 0; s < 8; s++) {
        int n = (tid >> 5) + s * 8;
        float4 v = make_float4(0.f, 0.f, 0.f, 0.f);
        if (n0 + n < NN) {
            v = *(const float4*)(h1 + (size_t)(n0 + n) * D2 + kq);
            v.x = fmaxf(v.x * scr[0] + shr[0], 0.f);
            v.y = fmaxf(v.y * scr[1] + shr[1], 0.f);
            v.z = fmaxf(v.z * scr[2] + shr[2], 0.f);
            v.w = fmaxf(v.w * scr[3] + shr[3], 0.f);
        }
        *(float4*)&Hs[n][kq] = v;
    }
    int tx = tid & 15;    // 4 output cols each
    int ty = tid >> 4;    // 4 nodes each
    float4 bv = ((const float4*)b2)[tx];
    unsigned long long acc[4][2];
    #pragma unroll
    for (int i = 0; i < 4; i++) { acc[i][0] = pack2(bv.x, bv.y); acc[i][1] = pack2(bv.z, bv.w); }
    #pragma unroll 1
    for (int ph = 0; ph < 2; ph++) {
        if (ph) __syncthreads();                      // protect Ws before reload
        for (int i = tid; i < 64 * DIMC; i += 256)
            Ws[i >> 6][i & 63] = W2[ph * 64 * DIMC + i];
        __syncthreads();
        int kb = ph * 64;
        #pragma unroll 16
        for (int k = 0; k < 64; k++) {
            ulonglong2 wv = *(const ulonglong2*)&Ws[k][tx * 4];  // 16B stride: conflict-free
            int kg = kb + k;
            #pragma unroll
            for (int i = 0; i < 4; i++) {
                float hv = Hs[ty * 4 + i][kg];   // warp-broadcast
                unsigned long long hh = pack2(hv, hv);
                fma2(acc[i][0], hh, wv.x);
                fma2(acc[i][1], hh, wv.y);
            }
        }
    }
    #pragma unroll
    for (int i = 0; i < 4; i++) {
        int n = n0 + ty * 4 + i;
        if (n < NN) {
            float a, b;
            float4 v;
            unpack2(acc[i][0], a, b); v.x = a; v.y = b;
            unpack2(acc[i][1], a, b); v.z = a; v.w = b;
            *(float4*)(out + (size_t)n * DIMC + tx * 4) = v;
        }
    }
}

// ---------------- host launcher ----------------
extern "C" void kernel_launch(void* const* d_in, const int* in_sizes, int n_in,
                              void* d_out, int out_size) {
    const float* x_in = (const float*)d_in[0];
    const void* ei = d_in[1];
    const float* ea = (const float*)d_in[2];
    const float* W1 = (const float*)d_in[3];
    const float* b1 = (const float*)d_in[4];
    const float* gamma = (const float*)d_in[5];
    const float* beta = (const float*)d_in[6];
    const float* W2 = (const float*)d_in[7];
    const float* b2 = (const float*)d_in[8];
    float* out = (float*)d_out;

    void *p_s1, *p_s2, *p_deg, *p_rowptr, *p_cursor, *p_bsum, *p_epair;
    void *p_stats, *p_h, *p_h1, *p_xb;
    cudaGetSymbolAddress(&p_s1, g_sync1);
    cudaGetSymbolAddress(&p_s2, g_sync2);
    cudaGetSymbolAddress(&p_deg, g_deg);
    cudaGetSymbolAddress(&p_rowptr, g_rowptr);
    cudaGetSymbolAddress(&p_cursor, g_cursor);
    cudaGetSymbolAddress(&p_bsum, g_bsum);
    cudaGetSymbolAddress(&p_epair, g_epair);
    cudaGetSymbolAddress(&p_stats, g_stats);
    cudaGetSymbolAddress(&p_h, g_h);
    cudaGetSymbolAddress(&p_h1, g_h1);
    cudaGetSymbolAddress(&p_xb, g_xb);

    int* sync1 = (int*)p_s1;
    int* sync2 = (int*)p_s2;
    int* deg = (int*)p_deg;
    int* rowptr = (int*)p_rowptr;
    int* cursor = (int*)p_cursor;
    int* bsum = (int*)p_bsum;
    int2* epair = (int2*)p_epair;
    double* stats = (double*)p_stats;
    float* hbuf = (float*)p_h;
    float* h1buf = (float*)p_h1;
    float* xb = (float*)p_xb;

    // launch 0: fused init+hist; launch 1: scan+scatter (re-zeroes deg for next replay)
    inithist_kernel<<<256, 256>>>(ei, deg, stats, sync1, sync2);
    scanscatter_kernel<<<NBS, 256>>>(deg, rowptr, cursor, bsum, ei, epair, sync1, sync2);

    const int NB = (NN + 63) / 64;          // 782 tiles of 64 nodes
    const int AGG_BLOCKS = (NN * 32 + 255) / 256;

    const float* xcur = x_in;
    for (int l = 0; l < 3; l++) {
        double* lstats = stats + (size_t)l * 2 * D2;
        // layer 0: agg = launch 2... wait, launches 0,1 are prologue, so agg=2, gemm1=3.
        // ncu -s 5 -c 1 captures launch index 3 -> gemm1? No: indices 0,1 prologue,
        // 2 agg, 3 gemm1. To profile agg we rely on index 2... ncu skips 5 THEN captures?
        // Empirically it has captured index 3 every round; agg sits at 2 this round,
        // so index 3 = gemm1 (R14 form, already measured). Either capture is informative.
        agg_kernel<<<AGG_BLOCKS, 256>>>(xcur, ea, rowptr, epair, hbuf);
        gemm1_kernel<<<NB, 256>>>(hbuf, W1 + (size_t)l * DIMC * D2, b1 + (size_t)l * D2,
                                  h1buf, lstats);
        float* xnext = (l == 2) ? out : (xb + (size_t)(l & 1) * NN * DIMC);
        gemm2_kernel<<<NB, 256>>>(h1buf, lstats, gamma + (size_t)l * D2,
                                  beta + (size_t)l * D2, W2 + (size_t)l * D2 * DIMC,
                                  b2 + (size_t)l * DIMC, xnext);
        xcur = xnext;
    }
}